// round 1
// baseline (speedup 1.0000x reference)
#include <cuda_runtime.h>
#include <cuda_bf16.h>

// Problem constants (fixed shapes per reference: B=4096 users, P=200 slots, tau=1.0)
#define NB 4096
#define PMAX 200
#define INV_TAU 1.0f
#define NTHREADS 256

// Scratch for per-user loss (no device allocation allowed -> __device__ global)
__device__ float g_block_loss[NB];

__device__ __forceinline__ float fast_rcp(float x) {
    float r;
    asm("rcp.approx.f32 %0, %1;" : "=f"(r) : "f"(x));
    return r;
}

// One block per user. Thread j owns column j (register N_j = exp(neg_j/tau)),
// loops rows i reading E_i = exp(pos_i/tau) from shared (broadcast LDS).
// Per pair: FADD + MUFU.RCP + FFMA  -> MUFU-bound at ~16 sigmoids/cyc/SM.
__global__ __launch_bounds__(NTHREADS) void sauc_pair_kernel(
    const float* __restrict__ scores_pos,
    const float* __restrict__ scores_neg,
    const int* __restrict__ pos_counts)
{
    const int b = blockIdx.x;
    const int tid = threadIdx.x;
    const int p = pos_counts[b];

    __shared__ float s_epos[PMAX];
    __shared__ float s_warp[NTHREADS / 32];

    // Precompute exponentials (O(p) work, one pass; p <= 200 < 256 threads)
    float Nj = 0.0f;
    if (tid < p) {
        s_epos[tid] = __expf(scores_pos[b * PMAX + tid] * INV_TAU);
        Nj = __expf(scores_neg[b * PMAX + tid] * INV_TAU);
    }
    __syncthreads();

    float acc = 0.0f;
    if (tid < p) {
        // Unrolled pair loop: acc += E_i / (E_i + N_j)
        int i = 0;
        #pragma unroll 1
        for (; i + 8 <= p; i += 8) {
            float e0 = s_epos[i + 0];
            float e1 = s_epos[i + 1];
            float e2 = s_epos[i + 2];
            float e3 = s_epos[i + 3];
            float e4 = s_epos[i + 4];
            float e5 = s_epos[i + 5];
            float e6 = s_epos[i + 6];
            float e7 = s_epos[i + 7];
            float r0 = fast_rcp(e0 + Nj);
            float r1 = fast_rcp(e1 + Nj);
            float r2 = fast_rcp(e2 + Nj);
            float r3 = fast_rcp(e3 + Nj);
            float r4 = fast_rcp(e4 + Nj);
            float r5 = fast_rcp(e5 + Nj);
            float r6 = fast_rcp(e6 + Nj);
            float r7 = fast_rcp(e7 + Nj);
            acc = fmaf(e0, r0, acc);
            acc = fmaf(e1, r1, acc);
            acc = fmaf(e2, r2, acc);
            acc = fmaf(e3, r3, acc);
            acc = fmaf(e4, r4, acc);
            acc = fmaf(e5, r5, acc);
            acc = fmaf(e6, r6, acc);
            acc = fmaf(e7, r7, acc);
        }
        for (; i < p; i++) {
            float e = s_epos[i];
            acc = fmaf(e, fast_rcp(e + Nj), acc);
        }
    }

    // Block reduction (all 256 threads participate; inactive ones carry 0)
    #pragma unroll
    for (int off = 16; off > 0; off >>= 1)
        acc += __shfl_down_sync(0xffffffffu, acc, off);
    if ((tid & 31) == 0) s_warp[tid >> 5] = acc;
    __syncthreads();
    if (tid < (NTHREADS / 32)) {
        float v = s_warp[tid];
        #pragma unroll
        for (int off = (NTHREADS / 64); off > 0; off >>= 1)
            v += __shfl_down_sync(0xffu, v, off);
        if (tid == 0) {
            float pf = (float)p;
            g_block_loss[b] = 1.0f - v / (pf * pf);
        }
    }
}

// Deterministic fixed-tree mean over the 4096 per-user losses.
__global__ __launch_bounds__(NTHREADS) void sauc_reduce_kernel(float* __restrict__ out)
{
    const int tid = threadIdx.x;
    __shared__ float s[NTHREADS];

    float a = 0.0f;
    #pragma unroll
    for (int i = tid; i < NB; i += NTHREADS)
        a += g_block_loss[i];
    s[tid] = a;
    __syncthreads();

    #pragma unroll
    for (int stride = NTHREADS / 2; stride >= 32; stride >>= 1) {
        if (tid < stride) s[tid] += s[tid + stride];
        __syncthreads();
    }
    if (tid < 32) {
        float v = s[tid];
        #pragma unroll
        for (int off = 16; off > 0; off >>= 1)
            v += __shfl_down_sync(0xffffffffu, v, off);
        if (tid == 0) out[0] = v * (1.0f / (float)NB);
    }
}

extern "C" void kernel_launch(void* const* d_in, const int* in_sizes, int n_in,
                              void* d_out, int out_size)
{
    const float* scores_pos = (const float*)d_in[0];
    const float* scores_neg = (const float*)d_in[1];
    const int*   pos_counts = (const int*)d_in[2];
    float* out = (float*)d_out;

    sauc_pair_kernel<<<NB, NTHREADS>>>(scores_pos, scores_neg, pos_counts);
    sauc_reduce_kernel<<<1, NTHREADS>>>(out);
}